// round 3
// baseline (speedup 1.0000x reference)
#include <cuda_runtime.h>
#include <math.h>

// 61x61 box local-contrast normalization, NHWC (16,1024,1024,2) fp32.
//
// R3 design: vertical window = per-thread O(1) sliding column sums C[4 chunks]
// (registers, coalesced loads); horizontal window = ONE warp scan of the
// current C state per emitted row (no scan work on priming rows).
//   Warp owns a 64-wide strip x 128 output rows. 128 maintained columns
//   (32-col halo each side). Per output row:
//     C += row[y+30] - row[y-31]        (cheap, coalesced)
//     P  = inclusive prefix of C        (4 chunk scans + carry chain)
//     W[o] = P[o+30] - P[o-31]          (predicated shuffles)
// Stage1: mid = x - W/7442.  Stage2 (on mid, mid^2): res = mid * rsqrt(var).

#define NIMG 16
#define HH   1024
#define WW   1024
#define RAD  30
#define SW   64                    // output strip width
#define SEG  128                   // output rows per warp
#define NSTRIP (WW / SW)           // 16
#define NVSEG  (HH / SEG)          // 8
#define WPB  4
#define NUNITS (NIMG * NSTRIP * NVSEG)   // 2048 warps
#define NBLK (NUNITS / WPB)              // 512 blocks
#define INV_D (1.0f / 7442.0f)     // 1/(61*61*2), denom includes C (TF ref)
#define EPS  1e-7f

__device__ float2 g_mid[(size_t)NIMG * HH * WW];   // 128MB scratch

__device__ __forceinline__ float2 shfl2(float2 v, int src) {
    float2 r;
    r.x = __shfl_sync(0xffffffffu, v.x, src);
    r.y = __shfl_sync(0xffffffffu, v.y, src);
    return r;
}

__device__ __forceinline__ void wscan2(float2& v, int lane) {
#pragma unroll
    for (int off = 1; off < 32; off <<= 1) {
        float ax = __shfl_up_sync(0xffffffffu, v.x, off);
        float ay = __shfl_up_sync(0xffffffffu, v.y, off);
        if (lane >= off) { v.x += ax; v.y += ay; }
    }
}

template<bool S2>
__global__ __launch_bounds__(WPB * 32)
void lcn_kernel(const float2* __restrict__ in, float2* __restrict__ out)
{
    const int lane = threadIdx.x & 31;
    const int unit = blockIdx.x * WPB + (threadIdx.x >> 5);

    const int img  = unit >> 7;             // 16 strips * 8 vsegs = 128 / image
    const int rem  = unit & 127;
    const int strip = rem & 15;
    const int vseg  = rem >> 4;

    const int gx0 = strip * SW;
    const int ys0 = vseg * SEG;

    const float2* __restrict__ src = in  + (size_t)img * HH * WW;
    float2*       __restrict__ dst = out + (size_t)img * HH * WW;

    int  col[4];
    bool cok[4];
#pragma unroll
    for (int c = 0; c < 4; ++c) {
        col[c] = gx0 - 32 + (c << 5) + lane;
        cok[c] = (unsigned)col[c] < (unsigned)WW;
    }

    const float2 Z = make_float2(0.f, 0.f);
    float2 Ca[4], Cb[4];
#pragma unroll
    for (int c = 0; c < 4; ++c) { Ca[c] = Z; if (S2) Cb[c] = Z; }

    // ---- priming: C = sum of rows [ys0-31 .. ys0+29] (cheap adds only) ----
    for (int it = 0; it < 61; ++it) {
        const int r = ys0 - 31 + it;
        if (r < 0) continue;
        const float2* rp = src + (size_t)r * WW;
#pragma unroll
        for (int c = 0; c < 4; ++c) {
            float2 e = cok[c] ? __ldg(rp + col[c]) : Z;
            Ca[c].x += e.x;  Ca[c].y += e.y;
            if (S2) { Cb[c].x += e.x * e.x;  Cb[c].y += e.y * e.y; }
        }
    }

    // extraction helpers
    const int  idx_hi  = (lane < 2)  ? lane + 30 : lane - 2;
    const bool pick_hi = (lane >= 2);
    const int  idx_lo  = (lane < 31) ? lane + 1  : 0;
    const bool pick_lo = (lane == 31);

    const int oc1 = gx0 + lane;
    const int oc2 = gx0 + 32 + lane;

    for (int k = 0; k < SEG; ++k) {
        const int yc    = ys0 + k;
        const int enter = yc + RAD;
        const int leave = yc - RAD - 1;
        const bool eok  = enter < HH;
        const bool lok  = leave >= 0;

        const float2* ep = src + (size_t)enter * WW;
        const float2* lp = src + (size_t)leave * WW;

        // slide vertical window
#pragma unroll
        for (int c = 0; c < 4; ++c) {
            float2 e = (eok && cok[c]) ? __ldg(ep + col[c]) : Z;
            float2 l = (lok && cok[c]) ? __ldg(lp + col[c]) : Z;
            float dx = e.x - l.x, dy = e.y - l.y;
            Ca[c].x += dx;  Ca[c].y += dy;
            if (S2) {
                // e^2 - l^2 = d * (e + l)
                Cb[c].x += dx * (e.x + l.x);
                Cb[c].y += dy * (e.y + l.y);
            }
        }

        // horizontal prefix of current C state
        float2 Pa[4], Pb[4];
#pragma unroll
        for (int c = 0; c < 4; ++c) {
            Pa[c] = Ca[c]; wscan2(Pa[c], lane);
            if (S2) { Pb[c] = Cb[c]; wscan2(Pb[c], lane); }
        }
        {   // carry chain
            float2 ca = Z, cb = Z;
#pragma unroll
            for (int c = 0; c < 4; ++c) {
                float2 ta = shfl2(Pa[c], 31);
                Pa[c].x += ca.x;  Pa[c].y += ca.y;
                ca.x += ta.x;     ca.y += ta.y;
                if (S2) {
                    float2 tb = shfl2(Pb[c], 31);
                    Pb[c].x += cb.x;  Pb[c].y += cb.y;
                    cb.x += tb.x;     cb.y += tb.y;
                }
            }
        }

        // 2-D box sums: W[o] = P[o+30] - P[o-31]
        float2 h1a_a = shfl2(Pa[1], idx_hi), h1a_b = shfl2(Pa[2], idx_hi);
        float2 l1a_a = shfl2(Pa[0], idx_lo), l1a_b = shfl2(Pa[1], idx_lo);
        float2 h2a_a = shfl2(Pa[2], idx_hi), h2a_b = shfl2(Pa[3], idx_hi);
        float2 l2a_a = shfl2(Pa[1], idx_lo), l2a_b = shfl2(Pa[2], idx_lo);
        float2 h1a = pick_hi ? h1a_b : h1a_a;
        float2 l1a = pick_lo ? l1a_b : l1a_a;
        float2 h2a = pick_hi ? h2a_b : h2a_a;
        float2 l2a = pick_lo ? l2a_b : l2a_a;
        float2 W1a = make_float2(h1a.x - l1a.x, h1a.y - l1a.y);
        float2 W2a = make_float2(h2a.x - l2a.x, h2a.y - l2a.y);

        const float2* cp = src + (size_t)yc * WW;
        float2 c1 = __ldg(cp + oc1);
        float2 c2 = __ldg(cp + oc2);
        float2* op = dst + (size_t)yc * WW;

        if (!S2) {
            op[oc1] = make_float2(c1.x - W1a.x * INV_D, c1.y - W1a.y * INV_D);
            op[oc2] = make_float2(c2.x - W2a.x * INV_D, c2.y - W2a.y * INV_D);
        } else {
            float2 h1b_a = shfl2(Pb[1], idx_hi), h1b_b = shfl2(Pb[2], idx_hi);
            float2 l1b_a = shfl2(Pb[0], idx_lo), l1b_b = shfl2(Pb[1], idx_lo);
            float2 h2b_a = shfl2(Pb[2], idx_hi), h2b_b = shfl2(Pb[3], idx_hi);
            float2 l2b_a = shfl2(Pb[1], idx_lo), l2b_b = shfl2(Pb[2], idx_lo);
            float2 h1b = pick_hi ? h1b_b : h1b_a;
            float2 l1b = pick_lo ? l1b_b : l1b_a;
            float2 h2b = pick_hi ? h2b_b : h2b_a;
            float2 l2b = pick_lo ? l2b_b : l2b_a;

            float q1x = (h1b.x - l1b.x) * INV_D, q1y = (h1b.y - l1b.y) * INV_D;
            float q2x = (h2b.x - l2b.x) * INV_D, q2y = (h2b.y - l2b.y) * INV_D;
            float m1x = W1a.x * INV_D, m1y = W1a.y * INV_D;
            float m2x = W2a.x * INV_D, m2y = W2a.y * INV_D;

            // res = mid * rsqrt(var); eps=1e-7 on denom is ~1e-7 rel -> negligible
            float v1x = fmaxf(q1x - m1x * m1x, 1e-12f);
            float v1y = fmaxf(q1y - m1y * m1y, 1e-12f);
            float v2x = fmaxf(q2x - m2x * m2x, 1e-12f);
            float v2y = fmaxf(q2y - m2y * m2y, 1e-12f);
            op[oc1] = make_float2(c1.x * rsqrtf(v1x), c1.y * rsqrtf(v1y));
            op[oc2] = make_float2(c2.x * rsqrtf(v2x), c2.y * rsqrtf(v2y));
        }
    }
}

extern "C" void kernel_launch(void* const* d_in, const int* in_sizes, int n_in,
                              void* d_out, int out_size)
{
    (void)in_sizes; (void)n_in; (void)out_size;
    const float2* x   = (const float2*)d_in[0];
    float2*       res = (float2*)d_out;

    float2* mid;
    cudaGetSymbolAddress((void**)&mid, g_mid);

    lcn_kernel<false><<<NBLK, WPB * 32>>>(x, mid);
    lcn_kernel<true ><<<NBLK, WPB * 32>>>(mid, res);
}

// round 5
// speedup vs baseline: 1.9080x; 1.9080x over previous
#include <cuda_runtime.h>
#include <math.h>

// 61x61 box local-contrast normalization, NHWC (16,1024,1024,2) fp32.
//
// R5 (= R4 re-bench, infra failed last round): vertical O(1) sliding column
// sums in registers; ONE warp scan of the current column-sum state per
// emitted row; 4096 warps for latency hiding; software prefetch of next
// iteration's enter/leave/center rows so LDG latency drains behind the
// shuffle scans.

#define NIMG 16
#define HH   1024
#define WW   1024
#define RAD  30
#define SW   64                    // output strip width
#define SEG  64                    // output rows per warp
#define NSTRIP (WW / SW)           // 16
#define NVSEG  (HH / SEG)          // 16
#define WPB  8
#define NUNITS (NIMG * NSTRIP * NVSEG)   // 4096 warps
#define NBLK (NUNITS / WPB)              // 512 blocks
#define INV_D (1.0f / 7442.0f)     // 1/(61*61*2), denom includes C (TF ref)

__device__ float2 g_mid[(size_t)NIMG * HH * WW];   // 128MB scratch

__device__ __forceinline__ float2 shfl2(float2 v, int src) {
    float2 r;
    r.x = __shfl_sync(0xffffffffu, v.x, src);
    r.y = __shfl_sync(0xffffffffu, v.y, src);
    return r;
}

__device__ __forceinline__ void wscan2(float2& v, int lane) {
#pragma unroll
    for (int off = 1; off < 32; off <<= 1) {
        float ax = __shfl_up_sync(0xffffffffu, v.x, off);
        float ay = __shfl_up_sync(0xffffffffu, v.y, off);
        if (lane >= off) { v.x += ax; v.y += ay; }
    }
}

template<bool S2>
__global__ __launch_bounds__(WPB * 32, 3)
void lcn_kernel(const float2* __restrict__ in, float2* __restrict__ out)
{
    const int lane = threadIdx.x & 31;
    const int unit = blockIdx.x * WPB + (threadIdx.x >> 5);

    const int img   = unit >> 8;            // 16 strips * 16 vsegs = 256/image
    const int rem   = unit & 255;
    const int strip = rem & 15;
    const int vseg  = rem >> 4;

    const int gx0 = strip * SW;
    const int ys0 = vseg * SEG;

    const float2* __restrict__ src = in  + (size_t)img * HH * WW;
    float2*       __restrict__ dst = out + (size_t)img * HH * WW;

    int  col[4];
    bool cok[4];
#pragma unroll
    for (int c = 0; c < 4; ++c) {
        col[c] = gx0 - 32 + (c << 5) + lane;
        cok[c] = (unsigned)col[c] < (unsigned)WW;
    }

    const float2 Z = make_float2(0.f, 0.f);
    float2 Ca[4], Cb[4];
#pragma unroll
    for (int c = 0; c < 4; ++c) { Ca[c] = Z; if (S2) Cb[c] = Z; }

    // ---- priming: C = sum of rows [ys0-31 .. ys0+29] (loads + adds only) ----
    for (int it = 0; it < 61; ++it) {
        const int r = ys0 - 31 + it;
        if (r < 0) continue;
        const float2* rp = src + (size_t)r * WW;
#pragma unroll
        for (int c = 0; c < 4; ++c) {
            float2 e = cok[c] ? __ldg(rp + col[c]) : Z;
            Ca[c].x += e.x;  Ca[c].y += e.y;
            if (S2) { Cb[c].x += e.x * e.x;  Cb[c].y += e.y * e.y; }
        }
    }

    // extraction helpers
    const int  idx_hi  = (lane < 2)  ? lane + 30 : lane - 2;
    const bool pick_hi = (lane >= 2);
    const int  idx_lo  = (lane < 31) ? lane + 1  : 0;
    const bool pick_lo = (lane == 31);

    const int oc1 = gx0 + lane;
    const int oc2 = gx0 + 32 + lane;

    // ---- prefetch for k = 0 ----
    float2 pe[4], pl[4], pc1, pc2;
    {
        const int enter = ys0 + RAD;              // < HH always (ys0 <= 960)
        const int leave = ys0 - RAD - 1;
        const bool lok  = leave >= 0;
        const float2* ep = src + (size_t)enter * WW;
        const float2* lp = src + (size_t)leave * WW;
#pragma unroll
        for (int c = 0; c < 4; ++c) {
            pe[c] = cok[c] ? __ldg(ep + col[c]) : Z;
            pl[c] = (lok && cok[c]) ? __ldg(lp + col[c]) : Z;
        }
        const float2* cp = src + (size_t)ys0 * WW;
        pc1 = __ldg(cp + oc1);
        pc2 = __ldg(cp + oc2);
    }

    for (int k = 0; k < SEG; ++k) {
        const int yc = ys0 + k;

        // consume prefetched rows: slide vertical window
#pragma unroll
        for (int c = 0; c < 4; ++c) {
            float dx = pe[c].x - pl[c].x, dy = pe[c].y - pl[c].y;
            Ca[c].x += dx;  Ca[c].y += dy;
            if (S2) {
                Cb[c].x += dx * (pe[c].x + pl[c].x);
                Cb[c].y += dy * (pe[c].y + pl[c].y);
            }
        }
        float2 c1 = pc1, c2 = pc2;

        // issue next-iteration loads now; they drain behind the scans
        if (k + 1 < SEG) {
            const int yn    = yc + 1;
            const int enter = yn + RAD;
            const int leave = yn - RAD - 1;
            const bool eok  = enter < HH;
            const bool lok  = leave >= 0;
            const float2* ep = src + (size_t)enter * WW;
            const float2* lp = src + (size_t)leave * WW;
#pragma unroll
            for (int c = 0; c < 4; ++c) {
                pe[c] = (eok && cok[c]) ? __ldg(ep + col[c]) : Z;
                pl[c] = (lok && cok[c]) ? __ldg(lp + col[c]) : Z;
            }
            const float2* cp = src + (size_t)yn * WW;
            pc1 = __ldg(cp + oc1);
            pc2 = __ldg(cp + oc2);
        }

        // horizontal prefix of current C state
        float2 Pa[4], Pb[4];
#pragma unroll
        for (int c = 0; c < 4; ++c) {
            Pa[c] = Ca[c]; wscan2(Pa[c], lane);
            if (S2) { Pb[c] = Cb[c]; wscan2(Pb[c], lane); }
        }
        {   // carry chain
            float2 ca = Z, cb = Z;
#pragma unroll
            for (int c = 0; c < 4; ++c) {
                float2 ta = shfl2(Pa[c], 31);
                Pa[c].x += ca.x;  Pa[c].y += ca.y;
                ca.x += ta.x;     ca.y += ta.y;
                if (S2) {
                    float2 tb = shfl2(Pb[c], 31);
                    Pb[c].x += cb.x;  Pb[c].y += cb.y;
                    cb.x += tb.x;     cb.y += tb.y;
                }
            }
        }

        // 2-D box sums: W[o] = P[o+30] - P[o-31]
        float2 h1a_a = shfl2(Pa[1], idx_hi), h1a_b = shfl2(Pa[2], idx_hi);
        float2 l1a_a = shfl2(Pa[0], idx_lo), l1a_b = shfl2(Pa[1], idx_lo);
        float2 h2a_a = shfl2(Pa[2], idx_hi), h2a_b = shfl2(Pa[3], idx_hi);
        float2 l2a_a = shfl2(Pa[1], idx_lo), l2a_b = shfl2(Pa[2], idx_lo);
        float2 h1a = pick_hi ? h1a_b : h1a_a;
        float2 l1a = pick_lo ? l1a_b : l1a_a;
        float2 h2a = pick_hi ? h2a_b : h2a_a;
        float2 l2a = pick_lo ? l2a_b : l2a_a;
        float2 W1a = make_float2(h1a.x - l1a.x, h1a.y - l1a.y);
        float2 W2a = make_float2(h2a.x - l2a.x, h2a.y - l2a.y);

        float2* op = dst + (size_t)yc * WW;

        if (!S2) {
            op[oc1] = make_float2(c1.x - W1a.x * INV_D, c1.y - W1a.y * INV_D);
            op[oc2] = make_float2(c2.x - W2a.x * INV_D, c2.y - W2a.y * INV_D);
        } else {
            float2 h1b_a = shfl2(Pb[1], idx_hi), h1b_b = shfl2(Pb[2], idx_hi);
            float2 l1b_a = shfl2(Pb[0], idx_lo), l1b_b = shfl2(Pb[1], idx_lo);
            float2 h2b_a = shfl2(Pb[2], idx_hi), h2b_b = shfl2(Pb[3], idx_hi);
            float2 l2b_a = shfl2(Pb[1], idx_lo), l2b_b = shfl2(Pb[2], idx_lo);
            float2 h1b = pick_hi ? h1b_b : h1b_a;
            float2 l1b = pick_lo ? l1b_b : l1b_a;
            float2 h2b = pick_hi ? h2b_b : h2b_a;
            float2 l2b = pick_lo ? l2b_b : l2b_a;

            float q1x = (h1b.x - l1b.x) * INV_D, q1y = (h1b.y - l1b.y) * INV_D;
            float q2x = (h2b.x - l2b.x) * INV_D, q2y = (h2b.y - l2b.y) * INV_D;
            float m1x = W1a.x * INV_D, m1y = W1a.y * INV_D;
            float m2x = W2a.x * INV_D, m2y = W2a.y * INV_D;

            float v1x = fmaxf(q1x - m1x * m1x, 1e-12f);
            float v1y = fmaxf(q1y - m1y * m1y, 1e-12f);
            float v2x = fmaxf(q2x - m2x * m2x, 1e-12f);
            float v2y = fmaxf(q2y - m2y * m2y, 1e-12f);
            op[oc1] = make_float2(c1.x * rsqrtf(v1x), c1.y * rsqrtf(v1y));
            op[oc2] = make_float2(c2.x * rsqrtf(v2x), c2.y * rsqrtf(v2y));
        }
    }
}

extern "C" void kernel_launch(void* const* d_in, const int* in_sizes, int n_in,
                              void* d_out, int out_size)
{
    (void)in_sizes; (void)n_in; (void)out_size;
    const float2* x   = (const float2*)d_in[0];
    float2*       res = (float2*)d_out;

    float2* mid;
    cudaGetSymbolAddress((void**)&mid, g_mid);

    lcn_kernel<false><<<NBLK, WPB * 32>>>(x, mid);
    lcn_kernel<true ><<<NBLK, WPB * 32>>>(mid, res);
}

// round 7
// speedup vs baseline: 2.0699x; 1.0848x over previous
#include <cuda_runtime.h>
#include <math.h>

// 61x61 box local-contrast normalization, NHWC (16,1024,1024,2) fp32.
//
// R7 (= R6 re-bench, infra failed last round): lane-blocked layout. Each lane
// owns 4 CONSECUTIVE columns (2x float4 loads). Horizontal prefix = 3 serial
// FADDs per lane + ONE warp scan of lane totals + 8 uniform-register
// cross-lane fetches for the window boundaries. Vertical window = O(1)
// per-thread sliding column sums. SHFL per emitted row: stage2 128 -> 52.

#define NIMG 16
#define HH   1024
#define WW   1024
#define RAD  30
#define SW   64                    // output strip width (cols 32..95 of tile)
#define SEG  64                    // output rows per warp
#define NSTRIP (WW / SW)           // 16
#define NVSEG  (HH / SEG)          // 16
#define WPB  4                     // warps per block (128 threads)
#define NUNITS (NIMG * NSTRIP * NVSEG)   // 4096 warps
#define NBLK (NUNITS / WPB)              // 1024 blocks
#define INV_D (1.0f / 7442.0f)     // 1/(61*61*2), denom includes C (TF ref)

__device__ float2 g_mid[(size_t)NIMG * HH * WW];   // 128MB scratch

__device__ __forceinline__ float2 shfl2(float2 v, int src) {
    float2 r;
    r.x = __shfl_sync(0xffffffffu, v.x, src);
    r.y = __shfl_sync(0xffffffffu, v.y, src);
    return r;
}

__device__ __forceinline__ void wscan2(float2& v, int lane) {
#pragma unroll
    for (int off = 1; off < 32; off <<= 1) {
        float ax = __shfl_up_sync(0xffffffffu, v.x, off);
        float ay = __shfl_up_sync(0xffffffffu, v.y, off);
        if (lane >= off) { v.x += ax; v.y += ay; }
    }
}

// load 4 consecutive float2 (2x float4) at float4-index i4 of row r4
__device__ __forceinline__ void load4(const float4* __restrict__ r4, int i4,
                                      bool ok, float2 v[4]) {
    if (ok) {
        float4 a = __ldg(r4 + i4);
        float4 b = __ldg(r4 + i4 + 1);
        v[0] = make_float2(a.x, a.y);
        v[1] = make_float2(a.z, a.w);
        v[2] = make_float2(b.x, b.y);
        v[3] = make_float2(b.z, b.w);
    } else {
        v[0] = v[1] = v[2] = v[3] = make_float2(0.f, 0.f);
    }
}

template<bool S2>
__global__ __launch_bounds__(WPB * 32, 5)
void lcn_kernel(const float2* __restrict__ in, float2* __restrict__ out)
{
    const int lane = threadIdx.x & 31;
    const int unit = blockIdx.x * WPB + (threadIdx.x >> 5);

    const int img   = unit >> 8;            // 16 strips * 16 vsegs per image
    const int rem   = unit & 255;
    const int strip = rem & 15;
    const int vseg  = rem >> 4;

    const int gx0 = strip * SW;             // first output col
    const int X0  = gx0 - 32;               // first tile col (32-col halo)
    const int ys0 = vseg * SEG;

    const float2* __restrict__ src = in  + (size_t)img * HH * WW;
    float2*       __restrict__ dst = out + (size_t)img * HH * WW;

    const int c0   = X0 + 4 * lane;         // lane's first col
    const bool lok = (unsigned)c0 < (unsigned)WW;   // whole-lane validity
    const int i4   = c0 >> 1;               // float4 index within row

    const bool act = (lane >= 8) && (lane < 24);    // output-owning lanes
    const int  oc  = gx0 + 4 * (lane - 8);          // first output col
    const int  o4  = oc >> 1;                        // float4 index

    const float2 Z = make_float2(0.f, 0.f);
    float2 Ca[4], Cb[4];
#pragma unroll
    for (int i = 0; i < 4; ++i) { Ca[i] = Z; if (S2) Cb[i] = Z; }

    // ---- priming: C = sum of rows [ys0-31 .. ys0+29] ----
    for (int it = 0; it < 61; ++it) {
        const int r = ys0 - 31 + it;
        if (r < 0) continue;
        const float4* r4 = (const float4*)(src + (size_t)r * WW);
        float2 e[4];
        load4(r4, i4, lok, e);
#pragma unroll
        for (int i = 0; i < 4; ++i) {
            Ca[i].x += e[i].x;  Ca[i].y += e[i].y;
            if (S2) { Cb[i].x += e[i].x * e[i].x;  Cb[i].y += e[i].y * e[i].y; }
        }
    }

    // ---- prefetch k = 0 ----
    float2 pe[4], pl[4], pc[4];
    {
        const int enter = ys0 + RAD;        // < HH always (ys0 <= 960)
        const int leave = ys0 - RAD - 1;
        load4((const float4*)(src + (size_t)enter * WW), i4, lok, pe);
        load4((const float4*)(src + (size_t)leave * WW), i4, lok && leave >= 0, pl);
        load4((const float4*)(src + (size_t)ys0 * WW), o4, act, pc);
    }

    for (int k = 0; k < SEG; ++k) {
        const int yc = ys0 + k;

        // consume prefetch: slide vertical window
#pragma unroll
        for (int i = 0; i < 4; ++i) {
            float dx = pe[i].x - pl[i].x, dy = pe[i].y - pl[i].y;
            Ca[i].x += dx;  Ca[i].y += dy;
            if (S2) {
                Cb[i].x += dx * (pe[i].x + pl[i].x);
                Cb[i].y += dy * (pe[i].y + pl[i].y);
            }
        }
        float2 cv[4];
#pragma unroll
        for (int i = 0; i < 4; ++i) cv[i] = pc[i];

        // issue next-iteration loads; drain behind scan
        if (k + 1 < SEG) {
            const int yn    = yc + 1;
            const int enter = yn + RAD;
            const int leave = yn - RAD - 1;
            load4((const float4*)(src + (size_t)enter * WW), i4,
                  lok && enter < HH, pe);
            load4((const float4*)(src + (size_t)leave * WW), i4,
                  lok && leave >= 0, pl);
            load4((const float4*)(src + (size_t)yn * WW), o4, act, pc);
        }

        // in-lane inclusive prefix (serial FADD)
        float2 Sa[4], Sb[4];
        Sa[0] = Ca[0];
#pragma unroll
        for (int i = 1; i < 4; ++i)
            Sa[i] = make_float2(Sa[i-1].x + Ca[i].x, Sa[i-1].y + Ca[i].y);
        if (S2) {
            Sb[0] = Cb[0];
#pragma unroll
            for (int i = 1; i < 4; ++i)
                Sb[i] = make_float2(Sb[i-1].x + Cb[i].x, Sb[i-1].y + Cb[i].y);
        }

        // warp scan of lane totals -> exclusive offset
        {
            float2 Ta = Sa[3], ia = Ta;
            wscan2(ia, lane);
            float2 offa = make_float2(ia.x - Ta.x, ia.y - Ta.y);
#pragma unroll
            for (int i = 0; i < 4; ++i) { Sa[i].x += offa.x; Sa[i].y += offa.y; }
            if (S2) {
                float2 Tb = Sb[3], ib = Tb;
                wscan2(ib, lane);
                float2 offb = make_float2(ib.x - Tb.x, ib.y - Tb.y);
#pragma unroll
                for (int i = 0; i < 4; ++i) { Sb[i].x += offb.x; Sb[i].y += offb.y; }
            }
        }

        // boundary fetches: W[i] = P[o_i + 30] - P[o_i - 31]
        //   o_i = c0 + i (outputs are the lane's own cols, lanes 8..23)
        float2 hA[4], lA[4];
        hA[0] = shfl2(Sa[2], lane + 7);
        hA[1] = shfl2(Sa[3], lane + 7);
        hA[2] = shfl2(Sa[0], lane + 8);
        hA[3] = shfl2(Sa[1], lane + 8);
        lA[0] = shfl2(Sa[1], lane - 8);
        lA[1] = shfl2(Sa[2], lane - 8);
        lA[2] = shfl2(Sa[3], lane - 8);
        lA[3] = shfl2(Sa[0], lane - 7);

        if (!S2) {
            if (act) {
                float4 r0, r1;
                float wx0 = hA[0].x - lA[0].x, wy0 = hA[0].y - lA[0].y;
                float wx1 = hA[1].x - lA[1].x, wy1 = hA[1].y - lA[1].y;
                float wx2 = hA[2].x - lA[2].x, wy2 = hA[2].y - lA[2].y;
                float wx3 = hA[3].x - lA[3].x, wy3 = hA[3].y - lA[3].y;
                r0.x = cv[0].x - wx0 * INV_D;  r0.y = cv[0].y - wy0 * INV_D;
                r0.z = cv[1].x - wx1 * INV_D;  r0.w = cv[1].y - wy1 * INV_D;
                r1.x = cv[2].x - wx2 * INV_D;  r1.y = cv[2].y - wy2 * INV_D;
                r1.z = cv[3].x - wx3 * INV_D;  r1.w = cv[3].y - wy3 * INV_D;
                float4* op4 = (float4*)(dst + (size_t)yc * WW);
                op4[o4]     = r0;
                op4[o4 + 1] = r1;
            }
        } else {
            float2 hB[4], lB[4];
            hB[0] = shfl2(Sb[2], lane + 7);
            hB[1] = shfl2(Sb[3], lane + 7);
            hB[2] = shfl2(Sb[0], lane + 8);
            hB[3] = shfl2(Sb[1], lane + 8);
            lB[0] = shfl2(Sb[1], lane - 8);
            lB[1] = shfl2(Sb[2], lane - 8);
            lB[2] = shfl2(Sb[3], lane - 8);
            lB[3] = shfl2(Sb[0], lane - 7);

            if (act) {
                float4 r0, r1;
#pragma unroll
                for (int i = 0; i < 4; ++i) {
                    float mx = (hA[i].x - lA[i].x) * INV_D;
                    float my = (hA[i].y - lA[i].y) * INV_D;
                    float qx = (hB[i].x - lB[i].x) * INV_D;
                    float qy = (hB[i].y - lB[i].y) * INV_D;
                    float vx = fmaxf(qx - mx * mx, 1e-12f);
                    float vy = fmaxf(qy - my * my, 1e-12f);
                    float ox = cv[i].x * rsqrtf(vx);
                    float oy = cv[i].y * rsqrtf(vy);
                    float* rr = (i < 2) ? &r0.x : &r1.x;
                    int    ii = (i < 2) ? i : i - 2;
                    rr[2*ii]   = ox;
                    rr[2*ii+1] = oy;
                }
                float4* op4 = (float4*)(dst + (size_t)yc * WW);
                op4[o4]     = r0;
                op4[o4 + 1] = r1;
            }
        }
    }
}

extern "C" void kernel_launch(void* const* d_in, const int* in_sizes, int n_in,
                              void* d_out, int out_size)
{
    (void)in_sizes; (void)n_in; (void)out_size;
    const float2* x   = (const float2*)d_in[0];
    float2*       res = (float2*)d_out;

    float2* mid;
    cudaGetSymbolAddress((void**)&mid, g_mid);

    lcn_kernel<false><<<NBLK, WPB * 32>>>(x, mid);
    lcn_kernel<true ><<<NBLK, WPB * 32>>>(mid, res);
}